// round 15
// baseline (speedup 1.0000x reference)
#include <cuda_runtime.h>
#include <cuda_fp16.h>
#include <cstdint>

// ---------------- problem constants ----------------
#define KTOT   3072
#define NOUT   12288
#define MB     64             // batch (GEMM N side)
#define MTILE  32             // output rows per CTA
#define KC     128            // K per chunk
#define NCHUNK (KTOT / KC)    // 24
#define NTH    256
#define NCTA   (NOUT / MTILE) // 384

// ---- smem layout ----
// B stages : 3 x (64 rows x 256B fp16, SW128 sub-rows) at 0       (48 KB)
// scales   : 3 x 512B                                   at 49152
// A packed : 2 x (32 rows x 128B int8)                  at 50688
// bias     : 128B                                       at 58880
#define SM_B(s)   ((uint32_t)(s) * 16384u)
#define SM_S(s)   (49152u + (uint32_t)(s) * 512u)
#define SM_APK(b) (50688u + (uint32_t)(b) * 4096u)
#define SM_BIAS   58880u
#define SMEM_TOTAL 59136u
#define EPI_RSTRIDE 36        // floats per epi row (144B, 16B-aligned)

// x pre-converted to fp16, k-permuted within every 16-half window so that
// hw kpair q maps to data k = 4q..4q+3 (matches packed-A word order).
__device__ __align__(16) __half g_xh[MB * KTOT];

__global__ void xconv_kernel(const float* __restrict__ x) {
    int i = blockIdx.x * blockDim.x + threadIdx.x;   // uint4 (8-half) index
    int w = i >> 1, h = i & 1;
    const float* base = x + (size_t)w * 16 + h * 2;
    __half hh[8];
#pragma unroll
    for (int q = 0; q < 4; q++) {
        float2 f = *(const float2*)(base + 4 * q);
        ((__half2*)hh)[q] = __floats2half2_rn(f.x, f.y);
    }
    ((uint4*)g_xh)[i] = *(uint4*)hh;
}

// ---------------- device helpers ----------------
__device__ __forceinline__ uint32_t smem_u32(const void* p) {
    uint32_t a;
    asm("{ .reg .u64 t; cvta.to.shared.u64 t, %1; cvt.u32.u64 %0, t; }" : "=r"(a) : "l"(p));
    return a;
}
__device__ __forceinline__ uint32_t swz(uint32_t off) {  // SW128 Swizzle<3,4,3>
    return off ^ ((off >> 3) & 0x70u);
}
__device__ __forceinline__ void cp_async16(uint32_t dst, const void* src) {
    asm volatile("cp.async.cg.shared.global [%0], [%1], 16;"
                 :: "r"(dst), "l"(src) : "memory");
}
#define CP_COMMIT()  asm volatile("cp.async.commit_group;" ::: "memory")
#define CP_WAIT(n)   asm volatile("cp.async.wait_group %0;" :: "n"(n) : "memory")

__device__ __forceinline__ void sts32(uint32_t addr, uint32_t v) {
    asm volatile("st.shared.b32 [%0], %1;" :: "r"(addr), "r"(v) : "memory");
}
__device__ __forceinline__ uint32_t lds32(uint32_t addr) {
    uint32_t v;
    asm volatile("ld.shared.b32 %0, [%1];" : "=r"(v) : "r"(addr));
    return v;
}
__device__ __forceinline__ void ldsm4(uint32_t* r, uint32_t addr) {
    asm volatile("ldmatrix.sync.aligned.m8n8.x4.shared.b16 {%0,%1,%2,%3}, [%4];"
                 : "=r"(r[0]), "=r"(r[1]), "=r"(r[2]), "=r"(r[3]) : "r"(addr));
}
__device__ __forceinline__ void mma16816(float* c,
                                         uint32_t a0, uint32_t a1, uint32_t a2, uint32_t a3,
                                         uint32_t b0, uint32_t b1) {
    asm volatile(
        "mma.sync.aligned.m16n8k16.row.col.f32.f16.f16.f32 "
        "{%0,%1,%2,%3}, {%4,%5,%6,%7}, {%8,%9}, {%0,%1,%2,%3};"
        : "+f"(c[0]), "+f"(c[1]), "+f"(c[2]), "+f"(c[3])
        : "r"(a0), "r"(a1), "r"(a2), "r"(a3), "r"(b0), "r"(b1));
}
__device__ __forceinline__ uint32_t pack4(int4 c) {   // low bytes of 4 codes
    uint32_t u = __byte_perm((uint32_t)c.x, (uint32_t)c.y, 0x0040);
    uint32_t v = __byte_perm((uint32_t)c.z, (uint32_t)c.w, 0x0040);
    return __byte_perm(u, v, 0x5410);
}
__device__ __forceinline__ uint32_t dq_h(uint32_t packed, uint32_t sel, __half2 s2) {
    const __half2 c1152 = __half2(__ushort_as_half((unsigned short)0x6480),
                                  __ushort_as_half((unsigned short)0x6480));
    uint32_t h = __byte_perm(packed, 0x64006400u, sel);
    __half2 v = __hmul2(__hsub2(*(__half2*)&h, c1152), s2);
    return *(uint32_t*)&v;
}

__global__ __launch_bounds__(NTH, 3)
void dql_kernel(const int*   __restrict__ wq,
                const float* __restrict__ ws,
                const int*   __restrict__ bq,
                const float* __restrict__ bs,
                float*       __restrict__ out) {
    extern __shared__ __align__(16) char smem[];
    const uint32_t sb = smem_u32(smem);
    float* smf = (float*)smem;

    const int tid  = threadIdx.x;
    const int lane = tid & 31;
    const int wid  = tid >> 5;
    const int wm   = wid & 1;      // output-row half (16)
    const int wn   = wid >> 1;     // batch quarter (16)
    const int cta  = blockIdx.x;

    if (tid < MTILE) {
        const int o = cta * MTILE + tid;
        ((float*)(smem + SM_BIAS))[tid] = ((float)bq[o] - 128.0f) * bs[o >> 5];
    }

    // ---- A producer: LDG raw codes, pack to int8, STS (XOR word layout) ----
    const int a_R = tid >> 3;      // 0..31 (weight row)
    const int a_s = tid & 7;       // 4-code segment within a 64-code half
    const int* a_src = wq + (size_t)(cta * MTILE + a_R) * KTOT + a_s * 4;
    const uint32_t a_pv = (uint32_t)(((a_R >> 1) & 3) << 2);
    uint32_t a_off[4];
#pragma unroll
    for (int kh = 0; kh < 2; kh++)
#pragma unroll
        for (int j = 0; j < 2; j++)
            a_off[kh * 2 + j] = (uint32_t)(a_R * 128 + kh * 64) +
                                ((((uint32_t)(a_s + 8 * j)) ^ a_pv) << 2);

    // ---- B + scales cp.async mapping ----
    const int brow = tid >> 2;     // 0..63 (batch row)
    const int bseg = tid & 3;
    const char* b_src0 = (const char*)(g_xh + (size_t)brow * KTOT);
    const float* s_src0 = ws + (size_t)(cta * MTILE + tid) * (KTOT / 32);
    uint32_t b_off[4];
#pragma unroll
    for (int kh = 0; kh < 2; kh++)
#pragma unroll
        for (int j = 0; j < 2; j++)
            b_off[kh * 2 + j] = swz((uint32_t)((brow * 2 + kh) * 128 +
                                               (bseg + 4 * j) * 16));

    auto issueB = [&](int c) {
        const uint32_t st = sb + SM_B(c % 3);
        const char* s = b_src0 + (size_t)c * (KC * 2);
        cp_async16(st + b_off[0], s + bseg * 16);
        cp_async16(st + b_off[1], s + (bseg + 4) * 16);
        cp_async16(st + b_off[2], s + 128 + bseg * 16);
        cp_async16(st + b_off[3], s + 128 + (bseg + 4) * 16);
        if (tid < MTILE)
            cp_async16(sb + SM_S(c % 3) + (uint32_t)(tid * 16), s_src0 + c * 4);
    };

    int4 ar[4];                    // A LDG staging (one chunk)
    auto ldgA = [&](int c) {
        const int* p = a_src + c * KC;
        ar[0] = *(const int4*)(p);
        ar[1] = *(const int4*)(p + 32);
        ar[2] = *(const int4*)(p + 64);
        ar[3] = *(const int4*)(p + 96);
    };
    auto stsA = [&](int c) {
        const uint32_t base = sb + SM_APK(c & 1);
        sts32(base + a_off[0], pack4(ar[0]));
        sts32(base + a_off[1], pack4(ar[1]));
        sts32(base + a_off[2], pack4(ar[2]));
        sts32(base + a_off[3], pack4(ar[3]));
    };

    float acc[2][4];
#pragma unroll
    for (int u = 0; u < 2; u++)
#pragma unroll
        for (int i = 0; i < 4; i++) acc[u][i] = 0.0f;

    // ---- consumer addressing ----
    const int g  = lane >> 2;
    const int q  = lane & 3;
    const int R0 = wm * 16 + g;                    // fragment rows R0, R0+8
    const uint32_t c_pv = (uint32_t)(((g >> 1) & 3) << 2);   // same for R0+8
    const uint32_t aw0  = (uint32_t)(R0 * 128);
    const uint32_t aw1  = (uint32_t)((R0 + 8) * 128);
    const uint32_t b_row2 = (uint32_t)((wn * 16 + (lane & 7) + ((lane >> 4) & 1) * 8) * 2);
    const uint32_t b_hcol = (uint32_t)(((lane >> 3) & 1) * 16);

    // ---- prologue ----
    issueB(0); CP_COMMIT();
    issueB(1); CP_COMMIT();
    ldgA(0); stsA(0);
    ldgA(1);

    for (int c = 0; c < NCHUNK; c++) {
        CP_WAIT(1);                  // B stage c complete
        __syncthreads();             // APK[c&1] visible; slot reuse safe

        if (c + 2 < NCHUNK) issueB(c + 2);
        CP_COMMIT();
        if (c + 1 < NCHUNK) {
            stsA(c + 1);
            if (c + 2 < NCHUNK) ldgA(c + 2);
        }

        const uint32_t APK = sb + SM_APK(c & 1);
        const uint32_t Bs  = sb + SM_B(c % 3);

        // scales: 4 blocks per row per chunk
        float4 s0 = *(const float4*)(smem + SM_S(c % 3) + (uint32_t)(R0 * 16));
        float4 s1 = *(const float4*)(smem + SM_S(c % 3) + (uint32_t)((R0 + 8) * 16));
        __half2 hs0[4] = { __float2half2_rn(s0.x), __float2half2_rn(s0.y),
                           __float2half2_rn(s0.z), __float2half2_rn(s0.w) };
        __half2 hs1[4] = { __float2half2_rn(s1.x), __float2half2_rn(s1.y),
                           __float2half2_rn(s1.z), __float2half2_rn(s1.w) };

#pragma unroll
        for (int t = 0; t < 8; t++) {
            const int kh = t >> 2, tt = t & 3;
            const uint32_t woff = (uint32_t)(kh * 64) +
                                  ((((uint32_t)(tt * 4 + q)) ^ c_pv) << 2);
            uint32_t p0 = lds32(APK + aw0 + woff);
            uint32_t p1 = lds32(APK + aw1 + woff);
            const __half2 sA = hs0[t >> 1];
            const __half2 sB = hs1[t >> 1];
            uint32_t a0 = dq_h(p0, 0x5150, sA);
            uint32_t a1 = dq_h(p1, 0x5150, sB);
            uint32_t a2 = dq_h(p0, 0x5352, sA);
            uint32_t a3 = dq_h(p1, 0x5352, sB);

            uint32_t bt[4];
            ldsm4(bt, Bs + swz((b_row2 + (uint32_t)kh) * 128u +
                               (uint32_t)(tt * 32) + b_hcol));

            mma16816(acc[0], a0, a1, a2, a3, bt[0], bt[1]);
            mma16816(acc[1], a0, a1, a2, a3, bt[2], bt[3]);
        }
    }

    // ---- epilogue: smem transpose + bias + coalesced stores ----
    __syncthreads();
    {
        const int orow = wm * 16 + g;
        const int mb   = wn * 16 + q * 2;
#pragma unroll
        for (int u = 0; u < 2; u++) {
            const int m = mb + u * 8;
            smf[m * EPI_RSTRIDE + orow]           = acc[u][0];
            smf[(m + 1) * EPI_RSTRIDE + orow]     = acc[u][1];
            smf[m * EPI_RSTRIDE + orow + 8]       = acc[u][2];
            smf[(m + 1) * EPI_RSTRIDE + orow + 8] = acc[u][3];
        }
    }
    __syncthreads();
    {
        const int m  = tid >> 2;      // batch row 0..63
        const int qq = tid & 3;       // 8-float segment
        const float* row  = smf + m * EPI_RSTRIDE + qq * 8;
        const float* bias = (const float*)(smem + SM_BIAS) + qq * 8;
        float* op = out + (size_t)m * NOUT + cta * MTILE + qq * 8;
        float4 v0 = *(const float4*)(row);
        float4 v1 = *(const float4*)(row + 4);
        float4 b0 = *(const float4*)(bias);
        float4 b1 = *(const float4*)(bias + 4);
        v0.x += b0.x; v0.y += b0.y; v0.z += b0.z; v0.w += b0.w;
        v1.x += b1.x; v1.y += b1.y; v1.z += b1.z; v1.w += b1.w;
        *(float4*)(op)     = v0;
        *(float4*)(op + 4) = v1;
    }
}

extern "C" void kernel_launch(void* const* d_in, const int* in_sizes, int n_in,
                              void* d_out, int out_size) {
    (void)in_sizes; (void)n_in; (void)out_size;
    xconv_kernel<<<(MB * KTOT / 8) / NTH, NTH>>>((const float*)d_in[0]);
    cudaFuncSetAttribute(dql_kernel, cudaFuncAttributeMaxDynamicSharedMemorySize, SMEM_TOTAL);
    dql_kernel<<<NCTA, NTH, SMEM_TOTAL>>>(
        (const int*)d_in[1],     // w_q
        (const float*)d_in[2],   // w_scales
        (const int*)d_in[3],     // b_q
        (const float*)d_in[4],   // b_scales
        (float*)d_out);
}